// round 2
// baseline (speedup 1.0000x reference)
#include <cuda_runtime.h>

#define N_NODES 50000
#define IN_CH   128
#define OUT_CH  64
#define N_EDGES 800000

// Scratch for projected features h = x @ W^T  (50000 x 64 f32 = 12.8 MB)
__device__ float g_h[N_NODES * OUT_CH];

// ---------------------------------------------------------------------------
// Kernel 1: h = x @ W^T
// One thread per node row; 64 f32 accumulators per thread.
// W (64x128 f32 = 32KB) staged in shared memory, read as float4 broadcasts.
// ---------------------------------------------------------------------------
__global__ void __launch_bounds__(128) gemm_kernel(
    const float* __restrict__ x,
    const float* __restrict__ W)
{
    __shared__ float4 Ws4[OUT_CH * IN_CH / 4];  // 2048 float4 = 32 KB

    const float4* Wg = reinterpret_cast<const float4*>(W);
    for (int i = threadIdx.x; i < OUT_CH * IN_CH / 4; i += blockDim.x)
        Ws4[i] = Wg[i];
    __syncthreads();

    int row = blockIdx.x * blockDim.x + threadIdx.x;
    if (row >= N_NODES) return;

    float acc[OUT_CH];
#pragma unroll
    for (int c = 0; c < OUT_CH; c++) acc[c] = 0.0f;

    const float4* xr = reinterpret_cast<const float4*>(x + (size_t)row * IN_CH);

    for (int k4 = 0; k4 < IN_CH / 4; k4++) {
        float4 xv = __ldg(xr + k4);
#pragma unroll
        for (int c = 0; c < OUT_CH; c++) {
            float4 w = Ws4[c * (IN_CH / 4) + k4];   // warp-uniform -> LDS broadcast
            acc[c] = fmaf(xv.x, w.x, acc[c]);
            acc[c] = fmaf(xv.y, w.y, acc[c]);
            acc[c] = fmaf(xv.z, w.z, acc[c]);
            acc[c] = fmaf(xv.w, w.w, acc[c]);
        }
    }

    float4* hr = reinterpret_cast<float4*>(g_h + (size_t)row * OUT_CH);
#pragma unroll
    for (int c4 = 0; c4 < OUT_CH / 4; c4++)
        hr[c4] = make_float4(acc[4 * c4 + 0], acc[4 * c4 + 1],
                             acc[4 * c4 + 2], acc[4 * c4 + 3]);
}

// ---------------------------------------------------------------------------
// Kernel 2: out[n][c] = bias[c]   (output is poisoned by the harness)
// ---------------------------------------------------------------------------
__global__ void init_out_kernel(const float* __restrict__ bias,
                                float* __restrict__ out)
{
    int i = blockIdx.x * blockDim.x + threadIdx.x;
    if (i < N_NODES * OUT_CH)
        out[i] = __ldg(bias + (i & (OUT_CH - 1)));
}

// ---------------------------------------------------------------------------
// Kernel 3: out[dst] += h[src]  for every edge.
// 16 threads per edge, each handles one float4 (4 channels):
//   gather float4 from h[src] (L2-resident), vector-reduce into out[dst]
//   via red.global.add.v4.f32 (REDG.128, no return value).
// NOTE: edge_index is int32 on device (JAX x64 disabled demotes int64->int32).
// ---------------------------------------------------------------------------
__global__ void __launch_bounds__(256) scatter_kernel(
    const int* __restrict__ ei,   // [2, N_EDGES] int32
    float* __restrict__ out)
{
    int t  = blockIdx.x * blockDim.x + threadIdx.x;
    int e  = t >> 4;           // edge id
    int c4 = t & 15;           // which float4 of the 64-ch row
    if (e >= N_EDGES) return;

    int src = __ldg(ei + e);
    int dst = __ldg(ei + N_EDGES + e);

    const float4* hrow = reinterpret_cast<const float4*>(g_h + (size_t)src * OUT_CH);
    float4 v = __ldg(hrow + c4);

    float* o = out + (size_t)dst * OUT_CH + c4 * 4;
    asm volatile("red.global.add.v4.f32 [%0], {%1, %2, %3, %4};"
                 :: "l"(o), "f"(v.x), "f"(v.y), "f"(v.z), "f"(v.w)
                 : "memory");
}

// ---------------------------------------------------------------------------
// Launch
// ---------------------------------------------------------------------------
extern "C" void kernel_launch(void* const* d_in, const int* in_sizes, int n_in,
                              void* d_out, int out_size)
{
    const float* x    = (const float*)d_in[0];      // [50000, 128] f32
    const int*   ei   = (const int*)d_in[1];        // [2, 800000] i32
    const float* W    = (const float*)d_in[2];      // [64, 128] f32
    const float* bias = (const float*)d_in[3];      // [64] f32
    float*       out  = (float*)d_out;              // [50000, 64] f32

    (void)in_sizes; (void)n_in; (void)out_size;

    // h = x @ W^T
    gemm_kernel<<<(N_NODES + 127) / 128, 128>>>(x, W);

    // out = bias (broadcast)
    init_out_kernel<<<(N_NODES * OUT_CH + 255) / 256, 256>>>(bias, out);

    // out[dst] += h[src]
    int total_threads = N_EDGES * 16;
    scatter_kernel<<<total_threads / 256, 256>>>(ei, out);
}